// round 1
// baseline (speedup 1.0000x reference)
#include <cuda_runtime.h>
#include <cuda_bf16.h>
#include <math.h>

// Problem constants
#define SEQ     4096
#define DIM     2048
#define NHEADS  16
#define HDIM    128
#define QKV_N   (3 * NHEADS * HDIM)   // 6144

// ---------------------------------------------------------------------------
// Scratch (device globals; no allocation allowed)
// ---------------------------------------------------------------------------
__device__ __align__(16) float g_xqkv[(size_t)SEQ * QKV_N];   // [4096, 6144]
__device__ __align__(16) float g_xo  [(size_t)SEQ * DIM];     // [4096, 2048]

// ---------------------------------------------------------------------------
// SGEMM: C[M,N] = A[M,K] @ B[K,N], all row-major fp32.
// 128x128 block tile, K-depth 8, 256 threads, 8x8 register micro-tile.
// ---------------------------------------------------------------------------
#define TM 128
#define TN 128
#define TK 8

__global__ __launch_bounds__(256, 2)
void sgemm_kernel(const float* __restrict__ A,
                  const float* __restrict__ B,
                  float* __restrict__ C,
                  int M, int N, int K)
{
    __shared__ float As[TK][TM];
    __shared__ float Bs[TK][TN];

    const int tid = threadIdx.x;        // 0..255
    const int tx  = tid & 15;           // 0..15
    const int ty  = tid >> 4;           // 0..15
    const int bm  = blockIdx.y * TM;
    const int bn  = blockIdx.x * TN;

    // Load mapping
    const int arow = tid >> 1;          // 0..127
    const int acol = (tid & 1) * 4;     // 0 or 4
    const int brow = tid >> 5;          // 0..7
    const int bcol = (tid & 31) * 4;    // 0..124

    const float* Aptr = A + (size_t)(bm + arow) * K + acol;
    const float* Bptr = B + (size_t)brow * N + bn + bcol;

    float acc[8][8];
#pragma unroll
    for (int i = 0; i < 8; i++)
#pragma unroll
        for (int j = 0; j < 8; j++) acc[i][j] = 0.f;

    for (int k0 = 0; k0 < K; k0 += TK) {
        float4 av = *(const float4*)(Aptr + k0);
        float4 bv = *(const float4*)(Bptr + (size_t)k0 * N);

        As[acol + 0][arow] = av.x;
        As[acol + 1][arow] = av.y;
        As[acol + 2][arow] = av.z;
        As[acol + 3][arow] = av.w;
        *(float4*)&Bs[brow][bcol] = bv;
        __syncthreads();

#pragma unroll
        for (int kk = 0; kk < TK; kk++) {
            float4 a0 = *(const float4*)&As[kk][ty * 8];
            float4 a1 = *(const float4*)&As[kk][ty * 8 + 4];
            float4 b0 = *(const float4*)&Bs[kk][tx * 8];
            float4 b1 = *(const float4*)&Bs[kk][tx * 8 + 4];
            float ra[8] = {a0.x, a0.y, a0.z, a0.w, a1.x, a1.y, a1.z, a1.w};
            float rb[8] = {b0.x, b0.y, b0.z, b0.w, b1.x, b1.y, b1.z, b1.w};
#pragma unroll
            for (int i = 0; i < 8; i++)
#pragma unroll
                for (int j = 0; j < 8; j++)
                    acc[i][j] = fmaf(ra[i], rb[j], acc[i][j]);
        }
        __syncthreads();
    }

    // Store 8x8 micro-tile as float4 pairs
#pragma unroll
    for (int i = 0; i < 8; i++) {
        float* crow = C + (size_t)(bm + ty * 8 + i) * N + bn + tx * 8;
        float4 c0 = {acc[i][0], acc[i][1], acc[i][2], acc[i][3]};
        float4 c1 = {acc[i][4], acc[i][5], acc[i][6], acc[i][7]};
        *(float4*)(crow)     = c0;
        *(float4*)(crow + 4) = c1;
    }
}

// ---------------------------------------------------------------------------
// Flash attention, fp32, unmasked softmax.
// Grid: (SEQ/BR, NHEADS). 256 threads. Br=Bc=64, d=128.
// Thread (r = tid>>2, c4 = tid&3): owns score cols [c4*16, c4*16+16) during
// S-phase and O cols {c4 + 4*cc : cc in [0,32)} during PV-phase (interleaved
// so Vs reads are bank-conflict-free).
// ---------------------------------------------------------------------------
#define BR 64
#define BC 64
#define KPAD 129   // padded row stride for Q/K/V tiles (odd -> <=2-way conflicts)
#define PPAD 65    // padded row stride for P tile

#define ATTN_SMEM_FLOATS (BR * KPAD + BC * KPAD + BC * KPAD + BR * PPAD)

__global__ __launch_bounds__(256, 1)
void attn_kernel(const float* __restrict__ xqkv, float* __restrict__ xo)
{
    extern __shared__ float sm[];
    float* Qs = sm;                        // [BR][KPAD]
    float* Ks = Qs + BR * KPAD;            // [BC][KPAD]
    float* Vs = Ks + BC * KPAD;            // [BC][KPAD]
    float* Ps = Vs + BC * KPAD;            // [BR][PPAD]

    const int h   = blockIdx.y;
    const int q0  = blockIdx.x * BR;
    const int tid = threadIdx.x;
    const int r   = tid >> 2;              // 0..63 (query row in tile)
    const int c4  = tid & 3;               // 0..3

    const float* Qg = xqkv + (size_t)q0 * QKV_N + h * HDIM;
    const float* Kg = xqkv + 2048 + h * HDIM;
    const float* Vg = xqkv + 4096 + h * HDIM;

    // Load Q tile (coalesced float4)
    for (int idx = tid * 4; idx < BR * HDIM; idx += 256 * 4) {
        int row = idx >> 7;
        int col = idx & 127;
        float4 v = *(const float4*)(Qg + (size_t)row * QKV_N + col);
        float* q = &Qs[row * KPAD + col];
        q[0] = v.x; q[1] = v.y; q[2] = v.z; q[3] = v.w;
    }

    float m = -INFINITY;
    float l = 0.f;
    float o[32];
#pragma unroll
    for (int cc = 0; cc < 32; cc++) o[cc] = 0.f;

    const float scale = 0.088388347648318447f;  // 1/sqrt(128)

    for (int kt = 0; kt < SEQ; kt += BC) {
        __syncthreads();  // covers Q load (iter 0) and Vs/Ps reuse (iter >0)

        // Load K,V tiles
        for (int idx = tid * 4; idx < BC * HDIM; idx += 256 * 4) {
            int row = idx >> 7;
            int col = idx & 127;
            size_t goff = (size_t)(kt + row) * QKV_N + col;
            float4 kv = *(const float4*)(Kg + goff);
            float4 vv = *(const float4*)(Vg + goff);
            float* kd = &Ks[row * KPAD + col];
            kd[0] = kv.x; kd[1] = kv.y; kd[2] = kv.z; kd[3] = kv.w;
            float* vd = &Vs[row * KPAD + col];
            vd[0] = vv.x; vd[1] = vv.y; vd[2] = vv.z; vd[3] = vv.w;
        }
        __syncthreads();

        // S-phase: 16 dot products of length 128 per thread
        float acc[16];
#pragma unroll
        for (int j = 0; j < 16; j++) acc[j] = 0.f;

        const float* qrow = &Qs[r * KPAD];
        const float* kbase = &Ks[(c4 * 16) * KPAD];
#pragma unroll 4
        for (int d = 0; d < HDIM; d++) {
            float qv = qrow[d];
#pragma unroll
            for (int j = 0; j < 16; j++)
                acc[j] = fmaf(qv, kbase[j * KPAD + d], acc[j]);
        }

        // scale + tile max
        float tmax = -INFINITY;
#pragma unroll
        for (int j = 0; j < 16; j++) {
            acc[j] *= scale;
            tmax = fmaxf(tmax, acc[j]);
        }
        tmax = fmaxf(tmax, __shfl_xor_sync(0xffffffffu, tmax, 1));
        tmax = fmaxf(tmax, __shfl_xor_sync(0xffffffffu, tmax, 2));

        float mnew = fmaxf(m, tmax);
        float corr = __expf(m - mnew);

        float lsum = 0.f;
#pragma unroll
        for (int j = 0; j < 16; j++) {
            float p = __expf(acc[j] - mnew);
            Ps[r * PPAD + c4 * 16 + j] = p;
            lsum += p;
        }
        lsum += __shfl_xor_sync(0xffffffffu, lsum, 1);
        lsum += __shfl_xor_sync(0xffffffffu, lsum, 2);

        l = l * corr + lsum;
        m = mnew;

#pragma unroll
        for (int cc = 0; cc < 32; cc++) o[cc] *= corr;

        __syncwarp();  // P row r shared only within the 4-lane group (same warp)

        // PV-phase: O[r][c4 + 4*cc] += sum_j P[r][j] * V[j][c4 + 4*cc]
        const float* prow = &Ps[r * PPAD];
#pragma unroll 4
        for (int j = 0; j < BC; j++) {
            float p = prow[j];
            const float* vrow = &Vs[j * KPAD + c4];
#pragma unroll
            for (int cc = 0; cc < 32; cc++)
                o[cc] = fmaf(p, vrow[4 * cc], o[cc]);
        }
    }

    // Normalize and write O
    float inv_l = 1.f / l;
    float* orow = xo + (size_t)(q0 + r) * DIM + h * HDIM + c4;
#pragma unroll
    for (int cc = 0; cc < 32; cc++)
        orow[4 * cc] = o[cc] * inv_l;
}

// ---------------------------------------------------------------------------
// Launch
// ---------------------------------------------------------------------------
extern "C" void kernel_launch(void* const* d_in, const int* in_sizes, int n_in,
                              void* d_out, int out_size)
{
    const float* x    = (const float*)d_in[0];   // [4096, 2048]
    const float* Wqkv = (const float*)d_in[1];   // [2048, 6144]
    const float* Wo   = (const float*)d_in[2];   // [2048, 2048]
    float* out = (float*)d_out;                  // [4096, 2048]

    float* xqkv = nullptr;
    float* xo   = nullptr;
    cudaGetSymbolAddress((void**)&xqkv, g_xqkv);
    cudaGetSymbolAddress((void**)&xo,   g_xo);

    // Allow >48KB dynamic smem for the attention kernel (idempotent host call,
    // not a stream op — safe under graph capture).
    static const size_t attn_smem = ATTN_SMEM_FLOATS * sizeof(float);
    cudaFuncSetAttribute(attn_kernel, cudaFuncAttributeMaxDynamicSharedMemorySize,
                         (int)attn_smem);

    // 1) xqkv = x @ Wqkv   [4096, 6144]
    {
        dim3 grid(QKV_N / TN, SEQ / TM);
        sgemm_kernel<<<grid, 256>>>(x, Wqkv, xqkv, SEQ, QKV_N, DIM);
    }

    // 2) flash attention -> xo [4096, 2048]
    {
        dim3 grid(SEQ / BR, NHEADS);
        attn_kernel<<<grid, 256, attn_smem>>>(xqkv, xo);
    }

    // 3) out = xo @ Wo    [4096, 2048]
    {
        dim3 grid(DIM / TN, SEQ / TM);
        sgemm_kernel<<<grid, 256>>>(xo, Wo, out, SEQ, DIM, DIM);
    }
}

// round 2
// speedup vs baseline: 4.9193x; 4.9193x over previous
#include <cuda_runtime.h>
#include <cstdint>
#include <math.h>

// ---------------------------------------------------------------------------
// Problem constants
// ---------------------------------------------------------------------------
#define SEQ     4096
#define DIM     2048
#define NHEADS  16
#define HDIM    128
#define QKV_N   6144

// Scratch (device globals; allocation is forbidden)
__device__ __align__(16) float g_xqkv[(size_t)SEQ * QKV_N];
__device__ __align__(16) float g_xo  [(size_t)SEQ * DIM];

// ---------------------------------------------------------------------------
// Small helpers
// ---------------------------------------------------------------------------
__device__ __forceinline__ uint32_t f2tf32(float x) {
    uint32_t r;
    asm("cvt.rna.tf32.f32 %0, %1;" : "=r"(r) : "f"(x));
    return r;
}

__device__ __forceinline__ void mma_tf32(float* c, const uint32_t* a, const uint32_t* b) {
    asm volatile(
        "mma.sync.aligned.m16n8k8.row.col.f32.tf32.tf32.f32 "
        "{%0,%1,%2,%3}, {%4,%5,%6,%7}, {%8,%9}, {%0,%1,%2,%3};"
        : "+f"(c[0]), "+f"(c[1]), "+f"(c[2]), "+f"(c[3])
        : "r"(a[0]), "r"(a[1]), "r"(a[2]), "r"(a[3]), "r"(b[0]), "r"(b[1]));
}

// FMA-only exp (avoids the MUFU pipe: 268M exps at MUFU rt=8 would cost ~2ms).
// Valid for x <= 0 (flash-softmax arguments). Rel err ~3e-6.
__device__ __forceinline__ float fast_exp(float x) {
    float t = fmaxf(x * 1.4426950408889634f, -126.0f);
    float z = t + 12582912.0f;            // round-to-nearest-int via magic number
    int   zi = __float_as_int(z);
    float n = z - 12582912.0f;
    float f = t - n;                      // f in [-0.5, 0.5]
    float p = fmaf(f, 1.3333558e-3f, 9.6181291e-3f);
    p = fmaf(f, p, 5.5504109e-2f);
    p = fmaf(f, p, 2.4022651e-1f);
    p = fmaf(f, p, 6.9314718e-1f);
    p = fmaf(f, p, 1.0f);
    // 2^n via exponent bit-splice: zi = 0x4B400000 + n  =>  (zi<<23)+0x3F800000 = bits(2^n)
    return __int_as_float((zi << 23) + 0x3F800000) * p;
}

__device__ __forceinline__ void cp_async16(uint32_t dst, const float* src) {
    asm volatile("cp.async.ca.shared.global [%0], [%1], 16;" :: "r"(dst), "l"(src));
}
__device__ __forceinline__ void cp_commit() { asm volatile("cp.async.commit_group;"); }
template<int N> __device__ __forceinline__ void cp_wait() {
    asm volatile("cp.async.wait_group %0;" :: "n"(N));
}

// ---------------------------------------------------------------------------
// TF32 GEMM: C[M,N] = A[M,K] @ B[K,N], fp32 in/out, tf32 tensor-core math.
// 128x128 block tile, K-chunk 32, 256 threads (8 warps, warp tile 64x32).
// cp.async double-buffered smem. Padded strides for conflict-free frag loads.
// ---------------------------------------------------------------------------
#define GKB 32
#define LDA 36     // (36*g + tig) % 32 bijective over the warp
#define LDB 136    // (136*tig + g) % 32 bijective over the warp
#define GEMM_SMEM_BYTES ((2 * 128 * LDA + 2 * GKB * LDB) * 4)

__global__ __launch_bounds__(256, 2)
void gemm_tf32(const float* __restrict__ A, const float* __restrict__ B,
               float* __restrict__ C, int M, int N, int K)
{
    extern __shared__ float gsm[];
    float* As = gsm;                        // [2][128*LDA]
    float* Bs = gsm + 2 * 128 * LDA;        // [2][GKB*LDB]

    const int tid  = threadIdx.x;
    const int lane = tid & 31;
    const int wid  = tid >> 5;
    const int g    = lane >> 2;
    const int tig  = lane & 3;
    const int rowW = (wid & 1) * 64;
    const int colW = (wid >> 1) * 32;
    const int bm = blockIdx.y * 128;
    const int bn = blockIdx.x * 128;

    const int arow = tid >> 1, acol = (tid & 1) * 16;
    const int brow = tid >> 3, bcol = (tid & 7) * 16;

    const uint32_t smem_s = (uint32_t)__cvta_generic_to_shared(gsm);
    const uint32_t a_dst0 = smem_s + (uint32_t)(arow * LDA + acol) * 4u;
    const uint32_t b_dst0 = smem_s + (uint32_t)(2 * 128 * LDA + brow * LDB + bcol) * 4u;

    const float* Ag = A + (size_t)(bm + arow) * K + acol;
    const float* Bg = B + (size_t)brow * N + bn + bcol;

    float acc[16][4];
#pragma unroll
    for (int i = 0; i < 16; i++) { acc[i][0] = acc[i][1] = acc[i][2] = acc[i][3] = 0.f; }

    const int nIter = K / GKB;

#define GEMM_ISSUE(IT, BUF) do {                                              \
        int _k0 = (IT) * GKB;                                                 \
        uint32_t _ad = a_dst0 + (uint32_t)((BUF) * 128 * LDA) * 4u;           \
        const float* _ap = Ag + _k0;                                          \
        _Pragma("unroll")                                                     \
        for (int _v = 0; _v < 4; _v++) cp_async16(_ad + _v * 16u, _ap + _v * 4); \
        uint32_t _bd = b_dst0 + (uint32_t)((BUF) * GKB * LDB) * 4u;           \
        const float* _bp = Bg + (size_t)_k0 * N;                              \
        _Pragma("unroll")                                                     \
        for (int _v = 0; _v < 4; _v++) cp_async16(_bd + _v * 16u, _bp + _v * 4); \
        cp_commit();                                                          \
    } while (0)

    GEMM_ISSUE(0, 0);

    for (int it = 0; it < nIter; ++it) {
        const int buf = it & 1;
        if (it + 1 < nIter) { GEMM_ISSUE(it + 1, buf ^ 1); cp_wait<1>(); }
        else                { cp_wait<0>(); }
        __syncthreads();

        const float* Ab = As + buf * 128 * LDA;
        const float* Bb = Bs + buf * GKB * LDB;

#pragma unroll
        for (int ks = 0; ks < GKB; ks += 8) {
            uint32_t af[4][4], bf[4][2];
#pragma unroll
            for (int mt = 0; mt < 4; mt++) {
                const float* ap = Ab + (rowW + mt * 16 + g) * LDA + ks;
                af[mt][0] = f2tf32(ap[tig]);
                af[mt][1] = f2tf32(ap[8 * LDA + tig]);
                af[mt][2] = f2tf32(ap[tig + 4]);
                af[mt][3] = f2tf32(ap[8 * LDA + tig + 4]);
            }
#pragma unroll
            for (int nt = 0; nt < 4; nt++) {
                const float* bp = Bb + (ks + tig) * LDB + colW + nt * 8 + g;
                bf[nt][0] = f2tf32(bp[0]);
                bf[nt][1] = f2tf32(bp[4 * LDB]);
            }
#pragma unroll
            for (int mt = 0; mt < 4; mt++)
#pragma unroll
                for (int nt = 0; nt < 4; nt++)
                    mma_tf32(acc[mt * 4 + nt], af[mt], bf[nt]);
        }
        __syncthreads();
    }

#pragma unroll
    for (int mt = 0; mt < 4; mt++) {
        const int r0 = bm + rowW + mt * 16 + g;
#pragma unroll
        for (int nt = 0; nt < 4; nt++) {
            float* p0 = C + (size_t)r0 * N + bn + colW + nt * 8 + 2 * tig;
            p0[0] = acc[mt * 4 + nt][0];
            p0[1] = acc[mt * 4 + nt][1];
            float* p1 = p0 + (size_t)8 * N;
            p1[0] = acc[mt * 4 + nt][2];
            p1[1] = acc[mt * 4 + nt][3];
        }
    }
#undef GEMM_ISSUE
}

// ---------------------------------------------------------------------------
// Flash attention, tf32 tensor cores. Br=128, Bc=64, d=128.
// 256 threads = 8 warps. S-phase warp tile 32x32 (4x2 layout over 128x64);
// PV-phase warp tile 32x64 (4x2 over 128x128). All operands tf32 in smem.
// ---------------------------------------------------------------------------
#define BR  128
#define BC  64
#define LDQ 132
#define LDK 132
#define LDV 136
#define LDP 68
#define ATTN_SMEM_WORDS (BR*LDQ + BC*LDK + BC*LDV + BR*LDP + 3*BR)
#define ATTN_SMEM_BYTES (ATTN_SMEM_WORDS * 4)

__global__ __launch_bounds__(256, 1)
void attn_tf32(const float* __restrict__ xqkv, float* __restrict__ xo)
{
    extern __shared__ float sm[];
    float* Qs     = sm;                     // [BR][LDQ] tf32 bits
    float* Ks     = Qs + BR * LDQ;          // [BC][LDK] tf32 bits
    float* Vs     = Ks + BC * LDK;          // [BC][LDV] tf32 bits
    float* Ps     = Vs + BC * LDV;          // [BR][LDP] raw S, then tf32 P
    float* m_s    = Ps + BR * LDP;          // [BR]
    float* l_s    = m_s + BR;               // [BR]
    float* corr_s = l_s + BR;               // [BR]

    const int tid  = threadIdx.x;
    const int lane = tid & 31;
    const int wid  = tid >> 5;
    const int g    = lane >> 2;
    const int tig  = lane & 3;
    const int wM   = wid >> 1;              // 0..3 -> 32-row band
    const int wN   = wid & 1;               // 0..1

    const int h  = blockIdx.y;
    const int q0 = blockIdx.x * BR;

    const float* Qg = xqkv + (size_t)q0 * QKV_N + h * HDIM;
    const float* Kg = xqkv + 2048 + h * HDIM;
    const float* Vg = xqkv + 4096 + h * HDIM;

    // Load + convert Q tile (128x128)
    {
        const int row = tid >> 1, c0 = (tid & 1) * 64;
        const float* src = Qg + (size_t)row * QKV_N + c0;
        float* dst = Qs + row * LDQ + c0;
#pragma unroll
        for (int v = 0; v < 16; v++) {
            float4 x = *(const float4*)(src + v * 4);
            float4 y = { __uint_as_float(f2tf32(x.x)), __uint_as_float(f2tf32(x.y)),
                         __uint_as_float(f2tf32(x.z)), __uint_as_float(f2tf32(x.w)) };
            *(float4*)(dst + v * 4) = y;
        }
    }
    if (tid < BR) { m_s[tid] = -INFINITY; l_s[tid] = 0.f; }

    float oacc[16][4];                      // [mt(2) * 8 + nt(8)][4]
#pragma unroll
    for (int i = 0; i < 16; i++) { oacc[i][0] = oacc[i][1] = oacc[i][2] = oacc[i][3] = 0.f; }

    const float scale = 0.08838834764831845f;   // 1/sqrt(128)

    for (int kt = 0; kt < SEQ; kt += BC) {
        __syncthreads();   // Ks/Vs free (prev PV + S done); covers Q/stat init on iter 0

        // Load + convert K,V tiles (64x128 each)
        {
            const int row = tid >> 2, c0 = (tid & 3) * 32;
            const float* ksrc = Kg + (size_t)(kt + row) * QKV_N + c0;
            const float* vsrc = Vg + (size_t)(kt + row) * QKV_N + c0;
            float* kd = Ks + row * LDK + c0;
            float* vd = Vs + row * LDV + c0;
#pragma unroll
            for (int v = 0; v < 8; v++) {
                float4 a = *(const float4*)(ksrc + v * 4);
                float4 b = *(const float4*)(vsrc + v * 4);
                float4 ka = { __uint_as_float(f2tf32(a.x)), __uint_as_float(f2tf32(a.y)),
                              __uint_as_float(f2tf32(a.z)), __uint_as_float(f2tf32(a.w)) };
                float4 vb = { __uint_as_float(f2tf32(b.x)), __uint_as_float(f2tf32(b.y)),
                              __uint_as_float(f2tf32(b.z)), __uint_as_float(f2tf32(b.w)) };
                *(float4*)(kd + v * 4) = ka;
                *(float4*)(vd + v * 4) = vb;
            }
        }
        __syncthreads();

        // ---- S phase: S[128x64] = Q @ K^T, warp tile 32x32 ----
        float sacc[8][4];
#pragma unroll
        for (int i = 0; i < 8; i++) { sacc[i][0] = sacc[i][1] = sacc[i][2] = sacc[i][3] = 0.f; }

#pragma unroll
        for (int kk = 0; kk < HDIM; kk += 8) {
            uint32_t af[2][4], bf[4][2];
#pragma unroll
            for (int mt = 0; mt < 2; mt++) {
                const float* ap = Qs + (32 * wM + mt * 16 + g) * LDQ + kk;
                af[mt][0] = __float_as_uint(ap[tig]);
                af[mt][1] = __float_as_uint(ap[8 * LDQ + tig]);
                af[mt][2] = __float_as_uint(ap[tig + 4]);
                af[mt][3] = __float_as_uint(ap[8 * LDQ + tig + 4]);
            }
#pragma unroll
            for (int nt = 0; nt < 4; nt++) {
                const float* bp = Ks + (32 * wN + nt * 8 + g) * LDK + kk;
                bf[nt][0] = __float_as_uint(bp[tig]);
                bf[nt][1] = __float_as_uint(bp[tig + 4]);
            }
#pragma unroll
            for (int mt = 0; mt < 2; mt++)
#pragma unroll
                for (int nt = 0; nt < 4; nt++)
                    mma_tf32(sacc[mt * 4 + nt], af[mt], bf[nt]);
        }

        // write raw scores to Ps
#pragma unroll
        for (int mt = 0; mt < 2; mt++)
#pragma unroll
            for (int nt = 0; nt < 4; nt++) {
                const int row = 32 * wM + mt * 16 + g;
                const int col = 32 * wN + nt * 8 + 2 * tig;
                float* p = Ps + row * LDP + col;
                p[0] = sacc[mt * 4 + nt][0];
                p[1] = sacc[mt * 4 + nt][1];
                float* q = p + 8 * LDP;
                q[0] = sacc[mt * 4 + nt][2];
                q[1] = sacc[mt * 4 + nt][3];
            }
        __syncthreads();

        // ---- softmax: 2 threads per row, 32 cols each ----
        {
            const int r = tid >> 1, c0 = (tid & 1) * 32;
            float* prow = Ps + r * LDP + c0;
            float v[32];
#pragma unroll
            for (int j = 0; j < 32; j += 4) {
                float4 x = *(const float4*)(prow + j);
                v[j] = x.x; v[j + 1] = x.y; v[j + 2] = x.z; v[j + 3] = x.w;
            }
            const float mold = m_s[r];
            float tmax = -INFINITY;
#pragma unroll
            for (int j = 0; j < 32; j++) { v[j] *= scale; tmax = fmaxf(tmax, v[j]); }
            tmax = fmaxf(tmax, __shfl_xor_sync(0xffffffffu, tmax, 1));
            const float mnew = fmaxf(mold, tmax);
            const float corr = fast_exp(mold - mnew);
            float lsum = 0.f;
#pragma unroll
            for (int j = 0; j < 32; j++) { v[j] = fast_exp(v[j] - mnew); lsum += v[j]; }
#pragma unroll
            for (int j = 0; j < 32; j += 4) {
                float4 x = { __uint_as_float(f2tf32(v[j])),     __uint_as_float(f2tf32(v[j + 1])),
                             __uint_as_float(f2tf32(v[j + 2])), __uint_as_float(f2tf32(v[j + 3])) };
                *(float4*)(prow + j) = x;
            }
            lsum += __shfl_xor_sync(0xffffffffu, lsum, 1);
            if ((tid & 1) == 0) {
                m_s[r] = mnew;
                l_s[r] = l_s[r] * corr + lsum;
                corr_s[r] = corr;
            }
        }
        __syncthreads();

        // ---- PV phase: O[128x128] += P @ V, warp tile 32x64 ----
        float c0m[2], c1m[2];
#pragma unroll
        for (int mt = 0; mt < 2; mt++) {
            c0m[mt] = corr_s[32 * wM + mt * 16 + g];
            c1m[mt] = corr_s[32 * wM + mt * 16 + g + 8];
        }
#pragma unroll
        for (int mt = 0; mt < 2; mt++)
#pragma unroll
            for (int nt = 0; nt < 8; nt++) {
                float* a = oacc[mt * 8 + nt];
                a[0] *= c0m[mt]; a[1] *= c0m[mt];
                a[2] *= c1m[mt]; a[3] *= c1m[mt];
            }

#pragma unroll
        for (int kk = 0; kk < BC; kk += 8) {
            uint32_t af[2][4], bf[8][2];
#pragma unroll
            for (int mt = 0; mt < 2; mt++) {
                const float* ap = Ps + (32 * wM + mt * 16 + g) * LDP + kk;
                af[mt][0] = __float_as_uint(ap[tig]);
                af[mt][1] = __float_as_uint(ap[8 * LDP + tig]);
                af[mt][2] = __float_as_uint(ap[tig + 4]);
                af[mt][3] = __float_as_uint(ap[8 * LDP + tig + 4]);
            }
#pragma unroll
            for (int nt = 0; nt < 8; nt++) {
                const float* bp = Vs + (kk + tig) * LDV + 64 * wN + nt * 8 + g;
                bf[nt][0] = __float_as_uint(bp[0]);
                bf[nt][1] = __float_as_uint(bp[4 * LDV]);
            }
#pragma unroll
            for (int mt = 0; mt < 2; mt++)
#pragma unroll
                for (int nt = 0; nt < 8; nt++)
                    mma_tf32(oacc[mt * 8 + nt], af[mt], bf[nt]);
        }
    }

    // ---- normalize + write O ----
#pragma unroll
    for (int mt = 0; mt < 2; mt++) {
        const int row = 32 * wM + mt * 16 + g;
        const float il0 = 1.f / l_s[row];
        const float il1 = 1.f / l_s[row + 8];
        float* out0 = xo + (size_t)(q0 + row) * DIM + h * HDIM + 64 * wN;
        float* out1 = out0 + (size_t)8 * DIM;
#pragma unroll
        for (int nt = 0; nt < 8; nt++) {
            const int c = nt * 8 + 2 * tig;
            out0[c]     = oacc[mt * 8 + nt][0] * il0;
            out0[c + 1] = oacc[mt * 8 + nt][1] * il0;
            out1[c]     = oacc[mt * 8 + nt][2] * il1;
            out1[c + 1] = oacc[mt * 8 + nt][3] * il1;
        }
    }
}

// ---------------------------------------------------------------------------
// Launch
// ---------------------------------------------------------------------------
extern "C" void kernel_launch(void* const* d_in, const int* in_sizes, int n_in,
                              void* d_out, int out_size)
{
    const float* x    = (const float*)d_in[0];   // [4096, 2048]
    const float* Wqkv = (const float*)d_in[1];   // [2048, 6144]
    const float* Wo   = (const float*)d_in[2];   // [2048, 2048]
    float* out = (float*)d_out;                  // [4096, 2048]

    float* xqkv = nullptr;
    float* xo   = nullptr;
    cudaGetSymbolAddress((void**)&xqkv, g_xqkv);
    cudaGetSymbolAddress((void**)&xo,   g_xo);

    cudaFuncSetAttribute(gemm_tf32, cudaFuncAttributeMaxDynamicSharedMemorySize,
                         GEMM_SMEM_BYTES);
    cudaFuncSetAttribute(attn_tf32, cudaFuncAttributeMaxDynamicSharedMemorySize,
                         ATTN_SMEM_BYTES);

    // 1) xqkv = x @ Wqkv : [4096, 6144]
    {
        dim3 grid(QKV_N / 128, SEQ / 128);
        gemm_tf32<<<grid, 256, GEMM_SMEM_BYTES>>>(x, Wqkv, xqkv, SEQ, QKV_N, DIM);
    }
    // 2) flash attention -> xo [4096, 2048]
    {
        dim3 grid(SEQ / BR, NHEADS);
        attn_tf32<<<grid, 256, ATTN_SMEM_BYTES>>>(xqkv, xo);
    }
    // 3) out = xo @ Wo : [4096, 2048]
    {
        dim3 grid(DIM / 128, SEQ / 128);
        gemm_tf32<<<grid, 256, GEMM_SMEM_BYTES>>>(xo, Wo, out, SEQ, DIM, DIM);
    }
}

// round 4
// speedup vs baseline: 5.6497x; 1.1485x over previous
#include <cuda_runtime.h>
#include <cstdint>
#include <math.h>

// ---------------------------------------------------------------------------
// Problem constants
// ---------------------------------------------------------------------------
#define SEQ     4096
#define DIM     2048
#define NHEADS  16
#define HDIM    128
#define QKV_N   6144

// ---------------------------------------------------------------------------
// Scratch (device globals; allocation is forbidden)
// ---------------------------------------------------------------------------
__device__ __align__(16) float g_xr    [(size_t)SEQ * DIM];     // x rounded to tf32
__device__ __align__(16) float g_wqkvr [(size_t)DIM * QKV_N];   // Wqkv rounded [2048,6144]
__device__ __align__(16) float g_wor   [(size_t)DIM * DIM];     // Wo rounded   [2048,2048]
__device__ __align__(16) float g_xqkv  [(size_t)SEQ * QKV_N];   // tf32-rounded GEMM1 out
__device__ __align__(16) float g_xo    [(size_t)SEQ * DIM];     // tf32-rounded attn out

// ---------------------------------------------------------------------------
// Helpers
// ---------------------------------------------------------------------------
__device__ __forceinline__ uint32_t f2tf32(float x) {
    uint32_t r;
    asm("cvt.rna.tf32.f32 %0, %1;" : "=r"(r) : "f"(x));
    return r;
}

__device__ __forceinline__ void mma_tf32(float* c, const uint32_t* a, const uint32_t* b) {
    asm volatile(
        "mma.sync.aligned.m16n8k8.row.col.f32.tf32.tf32.f32 "
        "{%0,%1,%2,%3}, {%4,%5,%6,%7}, {%8,%9}, {%0,%1,%2,%3};"
        : "+f"(c[0]), "+f"(c[1]), "+f"(c[2]), "+f"(c[3])
        : "r"(a[0]), "r"(a[1]), "r"(a[2]), "r"(a[3]), "r"(b[0]), "r"(b[1]));
}

__device__ __forceinline__ void cp_async16(uint32_t dst, const float* src) {
    asm volatile("cp.async.cg.shared.global [%0], [%1], 16;" :: "r"(dst), "l"(src));
}
__device__ __forceinline__ void cp_commit() { asm volatile("cp.async.commit_group;"); }
template<int N> __device__ __forceinline__ void cp_wait() {
    asm volatile("cp.async.wait_group %0;" :: "n"(N));
}

// FMA-only exp, valid for x <= 0 (flash-softmax args). Rel err ~3e-6.
// Avoids MUFU: 268M exps at MUFU rt_SMSP=8 would cost ~2 ms alone.
__device__ __forceinline__ float fast_exp(float x) {
    float t = fmaxf(x * 1.4426950408889634f, -126.0f);
    float z = t + 12582912.0f;
    int   zi = __float_as_int(z);
    float n = z - 12582912.0f;
    float f = t - n;
    float p = fmaf(f, 1.3333558e-3f, 9.6181291e-3f);
    p = fmaf(f, p, 5.5504109e-2f);
    p = fmaf(f, p, 2.4022651e-1f);
    p = fmaf(f, p, 6.9314718e-1f);
    p = fmaf(f, p, 1.0f);
    return __int_as_float((zi << 23) + 0x3F800000) * p;
}

// ---------------------------------------------------------------------------
// Prep: round fp32 -> tf32-valued fp32 (rna), elementwise.
// ---------------------------------------------------------------------------
__global__ void round_tf32_kernel(const float* __restrict__ in, float* __restrict__ out, int n4)
{
    int i = blockIdx.x * blockDim.x + threadIdx.x;
    if (i < n4) {
        float4 v = ((const float4*)in)[i];
        v.x = __uint_as_float(f2tf32(v.x));
        v.y = __uint_as_float(f2tf32(v.y));
        v.z = __uint_as_float(f2tf32(v.z));
        v.w = __uint_as_float(f2tf32(v.w));
        ((float4*)out)[i] = v;
    }
}

// ---------------------------------------------------------------------------
// TF32 GEMM: C[M,N] = A[M,K] @ B[K,N]. Inputs pre-rounded to tf32 values, so
// the hot loop is pure LDS+MMA (no CVT). 128x128 tile, K-chunk 32, 8 warps,
// warp tile 64x32, cp.async double-buffered. round_out!=0 -> tf32-round C.
// ---------------------------------------------------------------------------
#define GKB 32
#define LDA 36     // (36*g + tig) % 32 bijective over the warp
#define LDB 136    // (136*tig + g) % 32 bijective over the warp
#define GEMM_SMEM_BYTES ((2 * 128 * LDA + 2 * GKB * LDB) * 4)

__global__ __launch_bounds__(256, 2)
void gemm_tf32(const float* __restrict__ A, const float* __restrict__ B,
               float* __restrict__ C, int M, int N, int K, int round_out)
{
    extern __shared__ float gsm[];

    const int tid  = threadIdx.x;
    const int lane = tid & 31;
    const int wid  = tid >> 5;
    const int g    = lane >> 2;
    const int tig  = lane & 3;
    const int rowW = (wid & 1) * 64;
    const int colW = (wid >> 1) * 32;
    const int bm = blockIdx.y * 128;
    const int bn = blockIdx.x * 128;

    const int arow = tid >> 1, acol = (tid & 1) * 16;
    const int brow = tid >> 3, bcol = (tid & 7) * 16;

    const uint32_t smem_s = (uint32_t)__cvta_generic_to_shared(gsm);
    const uint32_t a_dst0 = smem_s + (uint32_t)(arow * LDA + acol) * 4u;
    const uint32_t b_dst0 = smem_s + (uint32_t)(2 * 128 * LDA + brow * LDB + bcol) * 4u;

    const float* Ag = A + (size_t)(bm + arow) * K + acol;
    const float* Bg = B + (size_t)brow * N + bn + bcol;

    float acc[16][4];
#pragma unroll
    for (int i = 0; i < 16; i++) { acc[i][0] = acc[i][1] = acc[i][2] = acc[i][3] = 0.f; }

    const int nIter = K / GKB;

#define GEMM_ISSUE(IT, BUF) do {                                              \
        int _k0 = (IT) * GKB;                                                 \
        uint32_t _ad = a_dst0 + (uint32_t)((BUF) * 128 * LDA) * 4u;           \
        const float* _ap = Ag + _k0;                                          \
        _Pragma("unroll")                                                     \
        for (int _v = 0; _v < 4; _v++) cp_async16(_ad + _v * 16u, _ap + _v * 4); \
        uint32_t _bd = b_dst0 + (uint32_t)((BUF) * GKB * LDB) * 4u;           \
        const float* _bp = Bg + (size_t)_k0 * N;                              \
        _Pragma("unroll")                                                     \
        for (int _v = 0; _v < 4; _v++) cp_async16(_bd + _v * 16u, _bp + _v * 4); \
        cp_commit();                                                          \
    } while (0)

    GEMM_ISSUE(0, 0);

    for (int it = 0; it < nIter; ++it) {
        const int buf = it & 1;
        if (it + 1 < nIter) { GEMM_ISSUE(it + 1, buf ^ 1); cp_wait<1>(); }
        else                { cp_wait<0>(); }
        __syncthreads();

        const float* Ab = gsm + buf * 128 * LDA;
        const float* Bb = gsm + 2 * 128 * LDA + buf * GKB * LDB;

#pragma unroll
        for (int ks = 0; ks < GKB; ks += 8) {
            uint32_t af[4][4], bf[4][2];
#pragma unroll
            for (int mt = 0; mt < 4; mt++) {
                const float* ap = Ab + (rowW + mt * 16 + g) * LDA + ks;
                af[mt][0] = __float_as_uint(ap[tig]);
                af[mt][1] = __float_as_uint(ap[8 * LDA + tig]);
                af[mt][2] = __float_as_uint(ap[tig + 4]);
                af[mt][3] = __float_as_uint(ap[8 * LDA + tig + 4]);
            }
#pragma unroll
            for (int nt = 0; nt < 4; nt++) {
                const float* bp = Bb + (ks + tig) * LDB + colW + nt * 8 + g;
                bf[nt][0] = __float_as_uint(bp[0]);
                bf[nt][1] = __float_as_uint(bp[4 * LDB]);
            }
#pragma unroll
            for (int mt = 0; mt < 4; mt++)
#pragma unroll
                for (int nt = 0; nt < 4; nt++)
                    mma_tf32(acc[mt * 4 + nt], af[mt], bf[nt]);
        }
        __syncthreads();
    }

#pragma unroll
    for (int mt = 0; mt < 4; mt++) {
        const int r0 = bm + rowW + mt * 16 + g;
#pragma unroll
        for (int nt = 0; nt < 4; nt++) {
            float v0 = acc[mt * 4 + nt][0], v1 = acc[mt * 4 + nt][1];
            float v2 = acc[mt * 4 + nt][2], v3 = acc[mt * 4 + nt][3];
            if (round_out) {
                v0 = __uint_as_float(f2tf32(v0));
                v1 = __uint_as_float(f2tf32(v1));
                v2 = __uint_as_float(f2tf32(v2));
                v3 = __uint_as_float(f2tf32(v3));
            }
            float* p0 = C + (size_t)r0 * N + bn + colW + nt * 8 + 2 * tig;
            p0[0] = v0;
            p0[1] = v1;
            float* p1 = p0 + (size_t)8 * N;
            p1[0] = v2;
            p1[1] = v3;
        }
    }
#undef GEMM_ISSUE
}

// ---------------------------------------------------------------------------
// Flash attention, tf32 mma.sync, cp.async-pipelined K/V.
// Br=128, Bc=64, d=128, 8 warps. Inputs (xqkv) pre-rounded to tf32 values by
// GEMM1's epilogue -> no input CVTs. K double-buffered, V single-buffered
// issued early (latency hidden behind S-phase + softmax).
// ---------------------------------------------------------------------------
#define BR  128
#define BC  64
#define NT  (SEQ / BC)
#define LDQ 132
#define LDK 132
#define LDV 136
#define LDP 68
// smem (words): Q[128][132] | K0[64][132] | K1[64][132] | V[64][136] | P[128][68] | stats
#define OFF_Q  0
#define OFF_K0 (BR * LDQ)
#define OFF_K1 (OFF_K0 + BC * LDK)
#define OFF_V  (OFF_K1 + BC * LDK)
#define OFF_P  (OFF_V + BC * LDV)
#define OFF_M  (OFF_P + BR * LDP)
#define OFF_L  (OFF_M + BR)
#define OFF_CR (OFF_L + BR)
#define ATTN_SMEM_WORDS (OFF_CR + BR)
#define ATTN_SMEM_BYTES (ATTN_SMEM_WORDS * 4)

__global__ __launch_bounds__(256, 1)
void attn_tf32(const float* __restrict__ xqkv, float* __restrict__ xo)
{
    extern __shared__ float sm[];
    float* Qs     = sm + OFF_Q;
    float* Ps     = sm + OFF_P;
    float* m_s    = sm + OFF_M;
    float* l_s    = sm + OFF_L;
    float* corr_s = sm + OFF_CR;

    const int tid  = threadIdx.x;
    const int lane = tid & 31;
    const int wid  = tid >> 5;
    const int g    = lane >> 2;
    const int tig  = lane & 3;
    const int wM   = wid >> 1;              // 0..3
    const int wN   = wid & 1;               // 0..1

    const int h  = blockIdx.y;
    const int q0 = blockIdx.x * BR;

    const float* Qg = xqkv + (size_t)q0 * QKV_N + h * HDIM;
    const float* Kg = xqkv + 2048 + h * HDIM;
    const float* Vg = xqkv + 4096 + h * HDIM;

    const uint32_t smem_b = (uint32_t)__cvta_generic_to_shared(sm);

    // --- prologue: async-load Q tile + K(0); one commit group ---
    {
        const int row = tid >> 1, c0 = (tid & 1) * 64;      // Q: 128 rows x 128 cols
        const uint32_t qd = smem_b + (uint32_t)(OFF_Q + row * LDQ + c0) * 4u;
        const float* qs = Qg + (size_t)row * QKV_N + c0;
#pragma unroll
        for (int j = 0; j < 16; j++) cp_async16(qd + j * 16u, qs + j * 4);

        const int krow = tid >> 2, kc0 = (tid & 3) * 32;    // K: 64 rows x 128 cols
        const uint32_t kd = smem_b + (uint32_t)(OFF_K0 + krow * LDK + kc0) * 4u;
        const float* ks = Kg + (size_t)krow * QKV_N + kc0;
#pragma unroll
        for (int j = 0; j < 8; j++) cp_async16(kd + j * 16u, ks + j * 4);
        cp_commit();
    }
    if (tid < BR) { m_s[tid] = -INFINITY; l_s[tid] = 0.f; }

    float oacc[16][4];
#pragma unroll
    for (int i = 0; i < 16; i++) { oacc[i][0] = oacc[i][1] = oacc[i][2] = oacc[i][3] = 0.f; }

    const float scale = 0.08838834764831845f;   // 1/sqrt(128)
    const int krow = tid >> 2, kc0 = (tid & 3) * 32;

    for (int t = 0; t < NT; ++t) {
        const int b = t & 1;
        __syncthreads();   // V buf free (PV(t-1) done); covers stats init on t=0

        // issue V(t) and K(t+1) as group G_t
        {
            const uint32_t vd = smem_b + (uint32_t)(OFF_V + krow * LDV + kc0) * 4u;
            const float* vs = Vg + (size_t)(t * BC + krow) * QKV_N + kc0;
#pragma unroll
            for (int j = 0; j < 8; j++) cp_async16(vd + j * 16u, vs + j * 4);
            if (t + 1 < NT) {
                const int koff = (b ? OFF_K0 : OFF_K1);
                const uint32_t kd = smem_b + (uint32_t)(koff + krow * LDK + kc0) * 4u;
                const float* ks = Kg + (size_t)((t + 1) * BC + krow) * QKV_N + kc0;
#pragma unroll
                for (int j = 0; j < 8; j++) cp_async16(kd + j * 16u, ks + j * 4);
            }
            cp_commit();
        }

        cp_wait<1>();      // G_{t-1} done -> K(t) (and Q on t=0) resident
        __syncthreads();

        const float* Ks = sm + (b ? OFF_K1 : OFF_K0);

        // ---- S phase: S[128x64] = Q @ K^T, warp tile 32x32 ----
        float sacc[8][4];
#pragma unroll
        for (int i = 0; i < 8; i++) { sacc[i][0] = sacc[i][1] = sacc[i][2] = sacc[i][3] = 0.f; }

#pragma unroll
        for (int kk = 0; kk < HDIM; kk += 8) {
            uint32_t af[2][4], bf[4][2];
#pragma unroll
            for (int mt = 0; mt < 2; mt++) {
                const float* ap = Qs + (32 * wM + mt * 16 + g) * LDQ + kk;
                af[mt][0] = __float_as_uint(ap[tig]);
                af[mt][1] = __float_as_uint(ap[8 * LDQ + tig]);
                af[mt][2] = __float_as_uint(ap[tig + 4]);
                af[mt][3] = __float_as_uint(ap[8 * LDQ + tig + 4]);
            }
#pragma unroll
            for (int nt = 0; nt < 4; nt++) {
                const float* bp = Ks + (32 * wN + nt * 8 + g) * LDK + kk;
                bf[nt][0] = __float_as_uint(bp[tig]);
                bf[nt][1] = __float_as_uint(bp[tig + 4]);
            }
#pragma unroll
            for (int mt = 0; mt < 2; mt++)
#pragma unroll
                for (int nt = 0; nt < 4; nt++)
                    mma_tf32(sacc[mt * 4 + nt], af[mt], bf[nt]);
        }

        // write raw scores to Ps
#pragma unroll
        for (int mt = 0; mt < 2; mt++)
#pragma unroll
            for (int nt = 0; nt < 4; nt++) {
                const int row = 32 * wM + mt * 16 + g;
                const int col = 32 * wN + nt * 8 + 2 * tig;
                float* p = Ps + row * LDP + col;
                p[0] = sacc[mt * 4 + nt][0];
                p[1] = sacc[mt * 4 + nt][1];
                float* q = p + 8 * LDP;
                q[0] = sacc[mt * 4 + nt][2];
                q[1] = sacc[mt * 4 + nt][3];
            }
        __syncthreads();

        // ---- softmax: 2 threads per row ----
        {
            const int r = tid >> 1, c0 = (tid & 1) * 32;
            float* prow = Ps + r * LDP + c0;
            float v[32];
#pragma unroll
            for (int j = 0; j < 32; j += 4) {
                float4 x = *(const float4*)(prow + j);
                v[j] = x.x; v[j + 1] = x.y; v[j + 2] = x.z; v[j + 3] = x.w;
            }
            const float mold = m_s[r];
            float tmax = -INFINITY;
#pragma unroll
            for (int j = 0; j < 32; j++) { v[j] *= scale; tmax = fmaxf(tmax, v[j]); }
            tmax = fmaxf(tmax, __shfl_xor_sync(0xffffffffu, tmax, 1));
            const float mnew = fmaxf(mold, tmax);
            const float corr = fast_exp(mold - mnew);
            float lsum = 0.f;
#pragma unroll
            for (int j = 0; j < 32; j++) { v[j] = fast_exp(v[j] - mnew); lsum += v[j]; }
#pragma unroll
            for (int j = 0; j < 32; j += 4) {
                float4 x = { __uint_as_float(f2tf32(v[j])),     __uint_as_float(f2tf32(v[j + 1])),
                             __uint_as_float(f2tf32(v[j + 2])), __uint_as_float(f2tf32(v[j + 3])) };
                *(float4*)(prow + j) = x;
            }
            lsum += __shfl_xor_sync(0xffffffffu, lsum, 1);
            if ((tid & 1) == 0) {
                m_s[r] = mnew;
                l_s[r] = l_s[r] * corr + lsum;
                corr_s[r] = corr;
            }
        }

        cp_wait<0>();      // G_t done -> V(t) resident
        __syncthreads();   // + P, stats visible

        const float* Vs = sm + OFF_V;

        // ---- PV phase: O[128x128] += P @ V, warp tile 32x64 ----
        float c0m[2], c1m[2];
#pragma unroll
        for (int mt = 0; mt < 2; mt++) {
            c0m[mt] = corr_s[32 * wM + mt * 16 + g];
            c1m[mt] = corr_s[32 * wM + mt * 16 + g + 8];
        }
#pragma unroll
        for (int mt = 0; mt < 2; mt++)
#pragma unroll
            for (int nt = 0; nt < 8; nt++) {
                float* a = oacc[mt * 8 + nt];
                a[0] *= c0m[mt]; a[1] *= c0m[mt];
                a[2] *= c1m[mt]; a[3] *= c1m[mt];
            }

#pragma unroll
        for (int kk = 0; kk < BC; kk += 8) {
            uint32_t af[2][4], bf[8][2];
#pragma unroll
            for (int mt = 0; mt < 2; mt++) {
                const float* ap = Ps + (32 * wM + mt * 16 + g) * LDP + kk;
                af[mt][0] = __float_as_uint(ap[tig]);
                af[mt][1] = __float_as_uint(ap[8 * LDP + tig]);
                af[mt][2] = __float_as_uint(ap[tig + 4]);
                af[mt][3] = __float_as_uint(ap[8 * LDP + tig + 4]);
            }
#pragma unroll
            for (int nt = 0; nt < 8; nt++) {
                const float* bp = Vs + (kk + tig) * LDV + 64 * wN + nt * 8 + g;
                bf[nt][0] = __float_as_uint(bp[0]);
                bf[nt][1] = __float_as_uint(bp[4 * LDV]);
            }
#pragma unroll
            for (int mt = 0; mt < 2; mt++)
#pragma unroll
                for (int nt = 0; nt < 8; nt++)
                    mma_tf32(oacc[mt * 8 + nt], af[mt], bf[nt]);
        }
    }

    // ---- normalize + write O (tf32-rounded: it is GEMM2's A operand) ----
#pragma unroll
    for (int mt = 0; mt < 2; mt++) {
        const int row = 32 * wM + mt * 16 + g;
        const float il0 = 1.f / l_s[row];
        const float il1 = 1.f / l_s[row + 8];
        float* out0 = xo + (size_t)(q0 + row) * DIM + h * HDIM + 64 * wN;
        float* out1 = out0 + (size_t)8 * DIM;
#pragma unroll
        for (int nt = 0; nt < 8; nt++) {
            const int c = nt * 8 + 2 * tig;
            out0[c]     = __uint_as_float(f2tf32(oacc[mt * 8 + nt][0] * il0));
            out0[c + 1] = __uint_as_float(f2tf32(oacc[mt * 8 + nt][1] * il0));
            out1[c]     = __uint_as_float(f2tf32(oacc[mt * 8 + nt][2] * il1));
            out1[c + 1] = __uint_as_float(f2tf32(oacc[mt * 8 + nt][3] * il1));
        }
    }
}

// ---------------------------------------------------------------------------
// Launch
// ---------------------------------------------------------------------------
extern "C" void kernel_launch(void* const* d_in, const int* in_sizes, int n_in,
                              void* d_out, int out_size)
{
    const float* x    = (const float*)d_in[0];   // [4096, 2048]
    const float* Wqkv = (const float*)d_in[1];   // [2048, 6144]
    const float* Wo   = (const float*)d_in[2];   // [2048, 2048]
    float* out = (float*)d_out;                  // [4096, 2048]

    float *xr, *wqkvr, *wor, *xqkv, *xo;
    cudaGetSymbolAddress((void**)&xr,    g_xr);
    cudaGetSymbolAddress((void**)&wqkvr, g_wqkvr);
    cudaGetSymbolAddress((void**)&wor,   g_wor);
    cudaGetSymbolAddress((void**)&xqkv,  g_xqkv);
    cudaGetSymbolAddress((void**)&xo,    g_xo);

    cudaFuncSetAttribute(gemm_tf32, cudaFuncAttributeMaxDynamicSharedMemorySize,
                         GEMM_SMEM_BYTES);
    cudaFuncSetAttribute(attn_tf32, cudaFuncAttributeMaxDynamicSharedMemorySize,
                         ATTN_SMEM_BYTES);

    // 0) prep: rna-round x, Wqkv, Wo to tf32 values (one-time; removes all
    //    in-loop CVTs from both GEMMs and the attention input path)
    round_tf32_kernel<<<(SEQ * DIM / 4) / 256, 256>>>(x, xr, SEQ * DIM / 4);
    round_tf32_kernel<<<(DIM * QKV_N / 4) / 256, 256>>>(Wqkv, wqkvr, DIM * QKV_N / 4);
    round_tf32_kernel<<<(DIM * DIM / 4) / 256, 256>>>(Wo, wor, DIM * DIM / 4);

    // 1) xqkv = x @ Wqkv (epilogue rounds to tf32 for the attention kernel)
    {
        dim3 grid(QKV_N / 128, SEQ / 128);
        gemm_tf32<<<grid, 256, GEMM_SMEM_BYTES>>>(xr, wqkvr, xqkv, SEQ, QKV_N, DIM, 1);
    }
    // 2) flash attention -> xo (tf32-rounded in epilogue)
    {
        dim3 grid(SEQ / BR, NHEADS);
        attn_tf32<<<grid, 256, ATTN_SMEM_BYTES>>>(xqkv, xo);
    }
    // 3) out = xo @ Wo (raw fp32 out)
    {
        dim3 grid(DIM / 128, SEQ / 128);
        gemm_tf32<<<grid, 256, GEMM_SMEM_BYTES>>>(xo, wor, out, SEQ, DIM, DIM, 0);
    }
}

// round 5
// speedup vs baseline: 5.7340x; 1.0149x over previous
#include <cuda_runtime.h>
#include <cstdint>
#include <math.h>

// ---------------------------------------------------------------------------
// Problem constants
// ---------------------------------------------------------------------------
#define SEQ     4096
#define DIM     2048
#define NHEADS  16
#define HDIM    128
#define QKV_N   6144

// ---------------------------------------------------------------------------
// Scratch (device globals; allocation is forbidden)
// ---------------------------------------------------------------------------
__device__ __align__(16) float g_xr    [(size_t)SEQ * DIM];     // x rounded to tf32
__device__ __align__(16) float g_wqkvT [(size_t)QKV_N * DIM];   // Wqkv^T rounded [6144][2048]
__device__ __align__(16) float g_woT   [(size_t)DIM * DIM];     // Wo^T rounded   [2048][2048]
__device__ __align__(16) float g_xqkv  [(size_t)SEQ * QKV_N];   // tf32-rounded GEMM1 out
__device__ __align__(16) float g_xo    [(size_t)SEQ * DIM];     // tf32-rounded attn out

// ---------------------------------------------------------------------------
// Helpers
// ---------------------------------------------------------------------------
__device__ __forceinline__ uint32_t f2tf32(float x) {
    uint32_t r;
    asm("cvt.rna.tf32.f32 %0, %1;" : "=r"(r) : "f"(x));
    return r;
}

__device__ __forceinline__ void mma_tf32(float* c, const uint32_t* a, const uint32_t* b) {
    asm volatile(
        "mma.sync.aligned.m16n8k8.row.col.f32.tf32.tf32.f32 "
        "{%0,%1,%2,%3}, {%4,%5,%6,%7}, {%8,%9}, {%0,%1,%2,%3};"
        : "+f"(c[0]), "+f"(c[1]), "+f"(c[2]), "+f"(c[3])
        : "r"(a[0]), "r"(a[1]), "r"(a[2]), "r"(a[3]), "r"(b[0]), "r"(b[1]));
}

// ldmatrix x4 on b16 view: one instruction = one tf32 m16k8 A-frag (or two
// k8n8 B-frags). Lane i supplies the 16B row address of tile (i>>3), row (i&7).
__device__ __forceinline__ void ldsm_x4(uint32_t* r, uint32_t addr) {
    asm volatile("ldmatrix.sync.aligned.m8n8.x4.shared.b16 {%0,%1,%2,%3}, [%4];"
                 : "=r"(r[0]), "=r"(r[1]), "=r"(r[2]), "=r"(r[3]) : "r"(addr));
}

__device__ __forceinline__ void cp_async16(uint32_t dst, const float* src) {
    asm volatile("cp.async.cg.shared.global [%0], [%1], 16;" :: "r"(dst), "l"(src));
}
__device__ __forceinline__ void cp_commit() { asm volatile("cp.async.commit_group;"); }
template<int N> __device__ __forceinline__ void cp_wait() {
    asm volatile("cp.async.wait_group %0;" :: "n"(N));
}

// FMA-only exp, valid for x <= 0. Rel err ~3e-6. Keeps MUFU idle.
__device__ __forceinline__ float fast_exp(float x) {
    float t = fmaxf(x * 1.4426950408889634f, -126.0f);
    float z = t + 12582912.0f;
    int   zi = __float_as_int(z);
    float n = z - 12582912.0f;
    float f = t - n;
    float p = fmaf(f, 1.3333558e-3f, 9.6181291e-3f);
    p = fmaf(f, p, 5.5504109e-2f);
    p = fmaf(f, p, 2.4022651e-1f);
    p = fmaf(f, p, 6.9314718e-1f);
    p = fmaf(f, p, 1.0f);
    return __int_as_float((zi << 23) + 0x3F800000) * p;
}

// ---------------------------------------------------------------------------
// Prep: elementwise rna-round; transpose+round for weights.
// ---------------------------------------------------------------------------
__global__ void round_tf32_kernel(const float* __restrict__ in, float* __restrict__ out, int n4)
{
    int i = blockIdx.x * blockDim.x + threadIdx.x;
    if (i < n4) {
        float4 v = ((const float4*)in)[i];
        v.x = __uint_as_float(f2tf32(v.x));
        v.y = __uint_as_float(f2tf32(v.y));
        v.z = __uint_as_float(f2tf32(v.z));
        v.w = __uint_as_float(f2tf32(v.w));
        ((float4*)out)[i] = v;
    }
}

// Wt[n][k] = round_tf32(W[k][n]); W is [K,N] row-major.
__global__ void transpose_round_kernel(const float* __restrict__ W, float* __restrict__ Wt,
                                       int K, int N)
{
    __shared__ float tile[32][33];
    const int n0 = blockIdx.x * 32;
    const int k0 = blockIdx.y * 32;
    const int tx = threadIdx.x, ty = threadIdx.y;
#pragma unroll
    for (int dy = ty; dy < 32; dy += 8)
        tile[dy][tx] = W[(size_t)(k0 + dy) * N + n0 + tx];
    __syncthreads();
#pragma unroll
    for (int dy = ty; dy < 32; dy += 8)
        Wt[(size_t)(n0 + dy) * K + k0 + tx] = __uint_as_float(f2tf32(tile[tx][dy]));
}

// ---------------------------------------------------------------------------
// TF32 GEMM: C[M,N] = A[M,K] @ Bt[N,K]^T. Both operands K-major, pre-rounded.
// 128x128 tile, K-chunk 32, 8 warps (warp tile 64x32), cp.async double-buffer,
// ldmatrix fragment loads (24 ldmatrix : 64 mma per warp-iter).
// ---------------------------------------------------------------------------
#define GKB 32
#define LDA 36          // stride%32==4 -> conflict-free ldmatrix phases
#define GEMM_SMEM_BYTES ((4 * 128 * LDA) * 4)   // 2 bufs x (A+B), 73728 B

__global__ __launch_bounds__(256, 2)
void gemm_tf32(const float* __restrict__ A, const float* __restrict__ Bt,
               float* __restrict__ C, int N, int K, int round_out)
{
    extern __shared__ float gsm[];

    const int tid  = threadIdx.x;
    const int lane = tid & 31;
    const int wid  = tid >> 5;
    const int g    = lane >> 2;
    const int tig  = lane & 3;
    const int rowW = (wid & 1) * 64;
    const int colW = (wid >> 1) * 32;
    const int bm = blockIdx.y * 128;
    const int bn = blockIdx.x * 128;

    // cp.async mapping: 128 rows x 32 k, 2 threads/row x 16 floats (same for A and B)
    const int crow = tid >> 1, ccol = (tid & 1) * 16;

    const uint32_t smem_s = (uint32_t)__cvta_generic_to_shared(gsm);
    const uint32_t a_dst0 = smem_s + (uint32_t)(crow * LDA + ccol) * 4u;
    const uint32_t b_dst0 = a_dst0 + 2u * 128u * LDA * 4u;

    const float* Ag = A  + (size_t)(bm + crow) * K + ccol;
    const float* Bg = Bt + (size_t)(bn + crow) * K + ccol;

    // ldmatrix lane address components
    const int arow_l = ((lane >> 3) & 1) * 8 + (lane & 7);   // A tiles: r0/r1 rows, r2/r3 rows
    const int acol_l = (lane >> 4) * 4;                      // word col 0 or 4
    const int brow_l = (lane >> 4) * 8 + (lane & 7);         // B tiles: n-block halves
    const int bcol_l = ((lane >> 3) & 1) * 4;

    const uint32_t a_lm0 = smem_s + (uint32_t)((rowW + arow_l) * LDA + acol_l) * 4u;
    const uint32_t b_lm0 = smem_s + 2u * 128u * LDA * 4u
                         + (uint32_t)((colW + brow_l) * LDA + bcol_l) * 4u;

    float acc[16][4];
#pragma unroll
    for (int i = 0; i < 16; i++) { acc[i][0] = acc[i][1] = acc[i][2] = acc[i][3] = 0.f; }

    const int nIter = K / GKB;

#define GEMM_ISSUE(IT, BUF) do {                                              \
        int _k0 = (IT) * GKB;                                                 \
        uint32_t _ad = a_dst0 + (uint32_t)((BUF) * 128 * LDA) * 4u;           \
        const float* _ap = Ag + _k0;                                          \
        _Pragma("unroll")                                                     \
        for (int _v = 0; _v < 4; _v++) cp_async16(_ad + _v * 16u, _ap + _v * 4); \
        uint32_t _bd = b_dst0 + (uint32_t)((BUF) * 128 * LDA) * 4u;           \
        const float* _bp = Bg + _k0;                                          \
        _Pragma("unroll")                                                     \
        for (int _v = 0; _v < 4; _v++) cp_async16(_bd + _v * 16u, _bp + _v * 4); \
        cp_commit();                                                          \
    } while (0)

    GEMM_ISSUE(0, 0);

    for (int it = 0; it < nIter; ++it) {
        const int buf = it & 1;
        if (it + 1 < nIter) { GEMM_ISSUE(it + 1, buf ^ 1); cp_wait<1>(); }
        else                { cp_wait<0>(); }
        __syncthreads();

        const uint32_t a_lm = a_lm0 + (uint32_t)(buf * 128 * LDA) * 4u;
        const uint32_t b_lm = b_lm0 + (uint32_t)(buf * 128 * LDA) * 4u;

#pragma unroll
        for (int ks = 0; ks < GKB; ks += 8) {
            uint32_t af[4][4], bf[4][2];
#pragma unroll
            for (int mt = 0; mt < 4; mt++)
                ldsm_x4(af[mt], a_lm + (uint32_t)(mt * 16 * LDA + ks) * 4u);
#pragma unroll
            for (int nt2 = 0; nt2 < 2; nt2++) {
                uint32_t t[4];
                ldsm_x4(t, b_lm + (uint32_t)(nt2 * 16 * LDA + ks) * 4u);
                bf[2 * nt2][0]     = t[0];
                bf[2 * nt2][1]     = t[1];
                bf[2 * nt2 + 1][0] = t[2];
                bf[2 * nt2 + 1][1] = t[3];
            }
#pragma unroll
            for (int mt = 0; mt < 4; mt++)
#pragma unroll
                for (int nt = 0; nt < 4; nt++)
                    mma_tf32(acc[mt * 4 + nt], af[mt], bf[nt]);
        }
        __syncthreads();
    }

#pragma unroll
    for (int mt = 0; mt < 4; mt++) {
        const int r0 = bm + rowW + mt * 16 + g;
#pragma unroll
        for (int nt = 0; nt < 4; nt++) {
            float v0 = acc[mt * 4 + nt][0], v1 = acc[mt * 4 + nt][1];
            float v2 = acc[mt * 4 + nt][2], v3 = acc[mt * 4 + nt][3];
            if (round_out) {
                v0 = __uint_as_float(f2tf32(v0));
                v1 = __uint_as_float(f2tf32(v1));
                v2 = __uint_as_float(f2tf32(v2));
                v3 = __uint_as_float(f2tf32(v3));
            }
            float* p0 = C + (size_t)r0 * N + bn + colW + nt * 8 + 2 * tig;
            p0[0] = v0;
            p0[1] = v1;
            float* p1 = p0 + (size_t)8 * N;
            p1[0] = v2;
            p1[1] = v3;
        }
    }
#undef GEMM_ISSUE
}

// ---------------------------------------------------------------------------
// Flash attention, tf32 mma.sync + ldmatrix for Q/K/P fragments.
// Br=128, Bc=64, d=128, 8 warps. K double-buffered cp.async, V single-buffer
// issued early. V fragments stay scalar LDS (k-major layout).
// ---------------------------------------------------------------------------
#define BR  128
#define BC  64
#define NT  (SEQ / BC)
#define LDQ 132    // %32==4 -> ldmatrix conflict-free
#define LDK 132
#define LDV 136
#define LDP 68     // %32==4
#define OFF_Q  0
#define OFF_K0 (BR * LDQ)
#define OFF_K1 (OFF_K0 + BC * LDK)
#define OFF_V  (OFF_K1 + BC * LDK)
#define OFF_P  (OFF_V + BC * LDV)
#define OFF_M  (OFF_P + BR * LDP)
#define OFF_L  (OFF_M + BR)
#define OFF_CR (OFF_L + BR)
#define ATTN_SMEM_WORDS (OFF_CR + BR)
#define ATTN_SMEM_BYTES (ATTN_SMEM_WORDS * 4)

__global__ __launch_bounds__(256, 1)
void attn_tf32(const float* __restrict__ xqkv, float* __restrict__ xo)
{
    extern __shared__ float sm[];
    float* Ps     = sm + OFF_P;
    float* m_s    = sm + OFF_M;
    float* l_s    = sm + OFF_L;
    float* corr_s = sm + OFF_CR;

    const int tid  = threadIdx.x;
    const int lane = tid & 31;
    const int wid  = tid >> 5;
    const int g    = lane >> 2;
    const int tig  = lane & 3;
    const int wM   = wid >> 1;              // 0..3
    const int wN   = wid & 1;               // 0..1

    const int h  = blockIdx.y;
    const int q0 = blockIdx.x * BR;

    const float* Qg = xqkv + (size_t)q0 * QKV_N + h * HDIM;
    const float* Kg = xqkv + 2048 + h * HDIM;
    const float* Vg = xqkv + 4096 + h * HDIM;

    const uint32_t smem_b = (uint32_t)__cvta_generic_to_shared(sm);

    // ldmatrix lane address components (same tile conventions as the GEMM)
    const int arow_l = ((lane >> 3) & 1) * 8 + (lane & 7);
    const int acol_l = (lane >> 4) * 4;
    const int brow_l = (lane >> 4) * 8 + (lane & 7);
    const int bcol_l = ((lane >> 3) & 1) * 4;

    const uint32_t q_lm = smem_b + (uint32_t)((OFF_Q) + (32 * wM + arow_l) * LDQ + acol_l) * 4u;
    const uint32_t p_lm = smem_b + (uint32_t)((OFF_P) + (32 * wM + arow_l) * LDP + acol_l) * 4u;
    const uint32_t k_lm_base = (uint32_t)((32 * wN + brow_l) * LDK + bcol_l) * 4u;

    // --- prologue: async-load Q tile + K(0) ---
    {
        const int row = tid >> 1, c0 = (tid & 1) * 64;
        const uint32_t qd = smem_b + (uint32_t)(OFF_Q + row * LDQ + c0) * 4u;
        const float* qs = Qg + (size_t)row * QKV_N + c0;
#pragma unroll
        for (int j = 0; j < 16; j++) cp_async16(qd + j * 16u, qs + j * 4);

        const int kr = tid >> 2, kc = (tid & 3) * 32;
        const uint32_t kd = smem_b + (uint32_t)(OFF_K0 + kr * LDK + kc) * 4u;
        const float* ks = Kg + (size_t)kr * QKV_N + kc;
#pragma unroll
        for (int j = 0; j < 8; j++) cp_async16(kd + j * 16u, ks + j * 4);
        cp_commit();
    }
    if (tid < BR) { m_s[tid] = -INFINITY; l_s[tid] = 0.f; }

    float oacc[16][4];
#pragma unroll
    for (int i = 0; i < 16; i++) { oacc[i][0] = oacc[i][1] = oacc[i][2] = oacc[i][3] = 0.f; }

    const float scale = 0.08838834764831845f;   // 1/sqrt(128)
    const int krow = tid >> 2, kc0 = (tid & 3) * 32;

    for (int t = 0; t < NT; ++t) {
        const int b = t & 1;
        __syncthreads();   // V buf free (PV(t-1) done); covers stats init on t=0

        // issue V(t) and K(t+1) as one commit group
        {
            const uint32_t vd = smem_b + (uint32_t)(OFF_V + krow * LDV + kc0) * 4u;
            const float* vs = Vg + (size_t)(t * BC + krow) * QKV_N + kc0;
#pragma unroll
            for (int j = 0; j < 8; j++) cp_async16(vd + j * 16u, vs + j * 4);
            if (t + 1 < NT) {
                const int koff = (b ? OFF_K0 : OFF_K1);
                const uint32_t kd = smem_b + (uint32_t)(koff + krow * LDK + kc0) * 4u;
                const float* ks = Kg + (size_t)((t + 1) * BC + krow) * QKV_N + kc0;
#pragma unroll
                for (int j = 0; j < 8; j++) cp_async16(kd + j * 16u, ks + j * 4);
            }
            cp_commit();
        }

        cp_wait<1>();      // previous group done -> K(t) (and Q on t=0) resident
        __syncthreads();

        const uint32_t k_lm = smem_b + (uint32_t)(b ? OFF_K1 : OFF_K0) * 4u + k_lm_base;

        // ---- S phase: S[128x64] = Q @ K^T, warp tile 32x32 ----
        float sacc[8][4];
#pragma unroll
        for (int i = 0; i < 8; i++) { sacc[i][0] = sacc[i][1] = sacc[i][2] = sacc[i][3] = 0.f; }

#pragma unroll
        for (int kk = 0; kk < HDIM; kk += 8) {
            uint32_t af[2][4], bf[4][2];
#pragma unroll
            for (int mt = 0; mt < 2; mt++)
                ldsm_x4(af[mt], q_lm + (uint32_t)(mt * 16 * LDQ + kk) * 4u);
#pragma unroll
            for (int nt2 = 0; nt2 < 2; nt2++) {
                uint32_t tr[4];
                ldsm_x4(tr, k_lm + (uint32_t)(nt2 * 16 * LDK + kk) * 4u);
                bf[2 * nt2][0]     = tr[0];
                bf[2 * nt2][1]     = tr[1];
                bf[2 * nt2 + 1][0] = tr[2];
                bf[2 * nt2 + 1][1] = tr[3];
            }
#pragma unroll
            for (int mt = 0; mt < 2; mt++)
#pragma unroll
                for (int nt = 0; nt < 4; nt++)
                    mma_tf32(sacc[mt * 4 + nt], af[mt], bf[nt]);
        }

        // write raw scores to Ps
#pragma unroll
        for (int mt = 0; mt < 2; mt++)
#pragma unroll
            for (int nt = 0; nt < 4; nt++) {
                const int row = 32 * wM + mt * 16 + g;
                const int col = 32 * wN + nt * 8 + 2 * tig;
                float* p = Ps + row * LDP + col;
                p[0] = sacc[mt * 4 + nt][0];
                p[1] = sacc[mt * 4 + nt][1];
                float* q = p + 8 * LDP;
                q[0] = sacc[mt * 4 + nt][2];
                q[1] = sacc[mt * 4 + nt][3];
            }
        __syncthreads();

        // ---- softmax: 2 threads per row ----
        {
            const int r = tid >> 1, c0 = (tid & 1) * 32;
            float* prow = Ps + r * LDP + c0;
            float v[32];
#pragma unroll
            for (int j = 0; j < 32; j += 4) {
                float4 x = *(const float4*)(prow + j);
                v[j] = x.x; v[j + 1] = x.y; v[j + 2] = x.z; v[j + 3] = x.w;
            }
            const float mold = m_s[r];
            float tmax = -INFINITY;
#pragma unroll
            for (int j = 0; j < 32; j++) { v[j] *= scale; tmax = fmaxf(tmax, v[j]); }
            tmax = fmaxf(tmax, __shfl_xor_sync(0xffffffffu, tmax, 1));
            const float mnew = fmaxf(mold, tmax);
            const float corr = fast_exp(mold - mnew);
            float lsum = 0.f;
#pragma unroll
            for (int j = 0; j < 32; j++) { v[j] = fast_exp(v[j] - mnew); lsum += v[j]; }
#pragma unroll
            for (int j = 0; j < 32; j += 4) {
                float4 x = { __uint_as_float(f2tf32(v[j])),     __uint_as_float(f2tf32(v[j + 1])),
                             __uint_as_float(f2tf32(v[j + 2])), __uint_as_float(f2tf32(v[j + 3])) };
                *(float4*)(prow + j) = x;
            }
            lsum += __shfl_xor_sync(0xffffffffu, lsum, 1);
            if ((tid & 1) == 0) {
                m_s[r] = mnew;
                l_s[r] = l_s[r] * corr + lsum;
                corr_s[r] = corr;
            }
        }

        cp_wait<0>();      // this iter's group done -> V(t) resident
        __syncthreads();   // + P, stats visible

        const float* Vs = sm + OFF_V;

        // ---- PV phase: O[128x128] += P @ V, warp tile 32x64 ----
        float c0m[2], c1m[2];
#pragma unroll
        for (int mt = 0; mt < 2; mt++) {
            c0m[mt] = corr_s[32 * wM + mt * 16 + g];
            c1m[mt] = corr_s[32 * wM + mt * 16 + g + 8];
        }
#pragma unroll
        for (int mt = 0; mt < 2; mt++)
#pragma unroll
            for (int nt = 0; nt < 8; nt++) {
                float* a = oacc[mt * 8 + nt];
                a[0] *= c0m[mt]; a[1] *= c0m[mt];
                a[2] *= c1m[mt]; a[3] *= c1m[mt];
            }

#pragma unroll
        for (int kk = 0; kk < BC; kk += 8) {
            uint32_t af[2][4], bf[8][2];
#pragma unroll
            for (int mt = 0; mt < 2; mt++)
                ldsm_x4(af[mt], p_lm + (uint32_t)(mt * 16 * LDP + kk) * 4u);
#pragma unroll
            for (int nt = 0; nt < 8; nt++) {
                const float* bp = Vs + (kk + tig) * LDV + 64 * wN + nt * 8 + g;
                bf[nt][0] = __float_as_uint(bp[0]);
                bf[nt][1] = __float_as_uint(bp[4 * LDV]);
            }
#pragma unroll
            for (int mt = 0; mt < 2; mt++)
#pragma unroll
                for (int nt = 0; nt < 8; nt++)
                    mma_tf32(oacc[mt * 8 + nt], af[mt], bf[nt]);
        }
    }

    // ---- normalize + write O (tf32-rounded: GEMM2's A operand) ----
#pragma unroll
    for (int mt = 0; mt < 2; mt++) {
        const int row = 32 * wM + mt * 16 + g;
        const float il0 = 1.f / l_s[row];
        const float il1 = 1.f / l_s[row + 8];
        float* out0 = xo + (size_t)(q0 + row) * DIM + h * HDIM + 64 * wN;
        float* out1 = out0 + (size_t)8 * DIM;
#pragma unroll
        for (int nt = 0; nt < 8; nt++) {
            const int c = nt * 8 + 2 * tig;
            out0[c]     = __uint_as_float(f2tf32(oacc[mt * 8 + nt][0] * il0));
            out0[c + 1] = __uint_as_float(f2tf32(oacc[mt * 8 + nt][1] * il0));
            out1[c]     = __uint_as_float(f2tf32(oacc[mt * 8 + nt][2] * il1));
            out1[c + 1] = __uint_as_float(f2tf32(oacc[mt * 8 + nt][3] * il1));
        }
    }
}

// ---------------------------------------------------------------------------
// Launch
// ---------------------------------------------------------------------------
extern "C" void kernel_launch(void* const* d_in, const int* in_sizes, int n_in,
                              void* d_out, int out_size)
{
    const float* x    = (const float*)d_in[0];   // [4096, 2048]
    const float* Wqkv = (const float*)d_in[1];   // [2048, 6144]
    const float* Wo   = (const float*)d_in[2];   // [2048, 2048]
    float* out = (float*)d_out;                  // [4096, 2048]

    float *xr, *wqkvT, *woT, *xqkv, *xo;
    cudaGetSymbolAddress((void**)&xr,    g_xr);
    cudaGetSymbolAddress((void**)&wqkvT, g_wqkvT);
    cudaGetSymbolAddress((void**)&woT,   g_woT);
    cudaGetSymbolAddress((void**)&xqkv,  g_xqkv);
    cudaGetSymbolAddress((void**)&xo,    g_xo);

    cudaFuncSetAttribute(gemm_tf32, cudaFuncAttributeMaxDynamicSharedMemorySize,
                         GEMM_SMEM_BYTES);
    cudaFuncSetAttribute(attn_tf32, cudaFuncAttributeMaxDynamicSharedMemorySize,
                         ATTN_SMEM_BYTES);

    // 0) prep: rna-round x; transpose+round Wqkv, Wo (K-major for ldmatrix GEMM)
    round_tf32_kernel<<<(SEQ * DIM / 4) / 256, 256>>>(x, xr, SEQ * DIM / 4);
    {
        dim3 blk(32, 8);
        transpose_round_kernel<<<dim3(QKV_N / 32, DIM / 32), blk>>>(Wqkv, wqkvT, DIM, QKV_N);
        transpose_round_kernel<<<dim3(DIM / 32, DIM / 32),  blk>>>(Wo,   woT,   DIM, DIM);
    }
    // 1) xqkv = x @ Wqkv (epilogue rounds to tf32 for attention)
    {
        dim3 grid(QKV_N / 128, SEQ / 128);
        gemm_tf32<<<grid, 256, GEMM_SMEM_BYTES>>>(xr, wqkvT, xqkv, QKV_N, DIM, 1);
    }
    // 2) flash attention -> xo (tf32-rounded)
    {
        dim3 grid(SEQ / BR, NHEADS);
        attn_tf32<<<grid, 256, ATTN_SMEM_BYTES>>>(xqkv, xo);
    }
    // 3) out = xo @ Wo (raw fp32 out)
    {
        dim3 grid(DIM / 128, SEQ / 128);
        gemm_tf32<<<grid, 256, GEMM_SMEM_BYTES>>>(xo, woT, out, DIM, DIM, 0);
    }
}